// round 9
// baseline (speedup 1.0000x reference)
#include <cuda_runtime.h>
#include <cuda_fp16.h>
#include <cstdint>

#define NROWS   131072
#define DIM     64
#define NE      1024
#define DECAYF  0.99f
#define ONE_M_D 0.01f
#define EPSF    1e-5f

// output layout (float32), tuple order of reference
#define OFF_Q    0
#define OFF_DIFF 8388608
#define OFF_IND  8388609
#define OFF_NCS  8519681
#define OFF_NEA  8520705
#define OFF_NE   8586241

// device scratch (statically zero-initialized; k2a/k2b re-zero after use)
__device__ float    g_count[NE];
__device__ float    g_esum[NE * DIM];
__device__ double   g_diff;
__device__ float    g_n;
// precomputed fp16 split of embed (col-major: [col][k-pair word])
__device__ uint32_t g_ebH[NE * 32];
__device__ uint32_t g_ebL[NE * 32];
__device__ float    g_en[NE];

// ------------------------------------------------------------------
__device__ __forceinline__ void mma_f16(float* c, const uint32_t* a, const uint32_t* b) {
    asm volatile(
        "mma.sync.aligned.m16n8k16.row.col.f32.f16.f16.f32 "
        "{%0,%1,%2,%3}, {%4,%5,%6,%7}, {%8,%9}, {%0,%1,%2,%3};"
        : "+f"(c[0]), "+f"(c[1]), "+f"(c[2]), "+f"(c[3])
        : "r"(a[0]), "r"(a[1]), "r"(a[2]), "r"(a[3]),
          "r"(b[0]), "r"(b[1]));
}
__device__ __forceinline__ void ldm4(uint32_t* r, uint32_t addr) {
    asm volatile("ldmatrix.sync.aligned.m8n8.x4.shared.b16 {%0,%1,%2,%3}, [%4];"
        : "=r"(r[0]), "=r"(r[1]), "=r"(r[2]), "=r"(r[3]) : "r"(addr));
}
__device__ __forceinline__ uint32_t h2(float a, float b) {
    __half2 h = __floats2half2_rn(a, b);
    return *(uint32_t*)&h;
}
__device__ __forceinline__ uint32_t smem_u32(const void* p) {
    uint32_t a;
    asm("{ .reg .u64 t; cvta.to.shared.u64 t, %1; cvt.u32.u64 %0, t; }" : "=r"(a) : "l"(p));
    return a;
}
__device__ __forceinline__ void cp16(uint32_t s, const void* g) {
    asm volatile("cp.async.cg.shared.global [%0], [%1], 16;" :: "r"(s), "l"(g));
}
#define CP_COMMIT() asm volatile("cp.async.commit_group;" ::: "memory")
#define CP_WAIT0()  asm volatile("cp.async.wait_group 0;" ::: "memory")

// ------------------------------------------------------------------
// SMEM (32-bit words): A [128 rows][68], B double buffer [64 cols][68] each
//   words 0..31 = fp16-hi pairs, 32..63 = fp16-lo pairs, 64..67 pad
#define WA 68
#define SM_A   0
#define SM_B0  (128 * WA)                  // 8704
#define SM_B1  (SM_B0 + 64 * WA)           // 13056
#define SMEM_WORDS (SM_B1 + 64 * WA)       // 17408
#define SMEM_BYTES (SMEM_WORDS * 4)        // 69632

#define NC 64
#define NCH 16

// ------------------------------------------------------------------
// k0: fp16-split of embed + col norms (runs once per launch)
// ------------------------------------------------------------------
__global__ void k0pre(const float* __restrict__ embed) {
    const int j = blockIdx.x * 128 + threadIdx.x;   // 1024 threads
    float en = 0.0f;
    #pragma unroll 8
    for (int w = 0; w < 32; w++) {
        float v0 = embed[(2 * w) * NE + j];
        float v1 = embed[(2 * w + 1) * NE + j];
        en = fmaf(v0, v0, fmaf(v1, v1, en));
        uint32_t hw = h2(v0, v1);
        __half2 hh = *(__half2*)&hw;
        float2 f = __half22float2(hh);
        g_ebH[j * 32 + w] = hw;
        g_ebL[j * 32 + w] = h2(v0 - f.x, v1 - f.y);
    }
    g_en[j] = en;
}

// ------------------------------------------------------------------
// k1: fused fp16-split MMA distance + argmin + stats (3 CTAs/SM)
// ------------------------------------------------------------------
__global__ void __launch_bounds__(256, 3) k1_main(
    const float* __restrict__ x,
    const float* __restrict__ embed,
    float* __restrict__ out)
{
    extern __shared__ uint32_t smw[];
    uint32_t* As = smw + SM_A;
    const uint32_t smbA  = smem_u32(smw);
    const uint32_t smbB0 = smbA + SM_B0 * 4;
    const uint32_t smbB1 = smbA + SM_B1 * 4;

    const int tid  = threadIdx.x;
    const int wid  = tid >> 5;
    const int lane = tid & 31;
    const int g    = lane >> 2;
    const int q    = lane & 3;
    const int wm   = wid >> 2;      // 0..1  (64-row half)
    const int wn   = wid & 3;       // 0..3  (16-col slice)
    const int rowBase = blockIdx.x * 128;

    // ---- prefetch B chunk 0 into buf0 (64 cols x 64 words) ----
    #pragma unroll
    for (int it = 0; it < 4; ++it) {
        const int task = tid + it * 256;          // 1024 tasks
        const int col = task >> 4, part = task & 15;
        const uint32_t dstW = col * WA + (part < 8 ? part * 4 : 32 + (part - 8) * 4);
        const uint32_t* src = (part < 8 ? g_ebH + (size_t)col * 32 + part * 4
                                        : g_ebL + (size_t)col * 32 + (part - 8) * 4);
        cp16(smbB0 + dstW * 4, src);
    }
    CP_COMMIT();

    // ---- load A: fp16 split of x tile ----
    {
        const int r = tid >> 1, half = tid & 1;
        const float4* xg = (const float4*)(x + (size_t)(rowBase + r) * DIM) + half * 8;
        uint32_t* dA = As + r * WA + half * 16;
        #pragma unroll
        for (int i = 0; i < 8; i++) {
            float4 v = xg[i];
            uint32_t hxy = h2(v.x, v.y), hzw = h2(v.z, v.w);
            __half2 hh0 = *(__half2*)&hxy, hh1 = *(__half2*)&hzw;
            float2 f0 = __half22float2(hh0), f1 = __half22float2(hh1);
            dA[2 * i]          = hxy;
            dA[2 * i + 1]      = hzw;
            dA[32 + 2 * i]     = h2(v.x - f0.x, v.y - f0.y);
            dA[32 + 2 * i + 1] = h2(v.z - f1.x, v.w - f1.y);
        }
    }

    // per-lane ldmatrix addresses
    const int r8  = lane & 7;
    const int sel = lane >> 3;      // 0..3
    const uint32_t aAddr0 = smbA +
        (uint32_t)((wm * 64 + r8 + (sel & 1) * 8) * WA + (sel >> 1) * 4) * 4;
    const uint32_t bOff = (uint32_t)((wn * 16 + r8 + (sel >> 1) * 8) * WA + (sel & 1) * 4) * 4;

    float best[8];
    int   bidx[8];
    #pragma unroll
    for (int i = 0; i < 8; i++) { best[i] = -3.4e38f; bidx[i] = 0; }

    for (int c = 0; c < NCH; c++) {
        const int cb = c * NC;
        const uint32_t bufR = (c & 1) ? smbB1 : smbB0;
        const uint32_t bufW = (c & 1) ? smbB0 : smbB1;

        CP_WAIT0();
        __syncthreads();

        // ---- prefetch chunk c+1 (other buffer), overlaps MMA ----
        if (c < NCH - 1) {
            const int ncb = cb + NC;
            #pragma unroll
            for (int it = 0; it < 4; ++it) {
                const int task = tid + it * 256;
                const int col = task >> 4, part = task & 15;
                const uint32_t dstW = col * WA + (part < 8 ? part * 4 : 32 + (part - 8) * 4);
                const uint32_t* src = (part < 8
                    ? g_ebH + (size_t)(ncb + col) * 32 + part * 4
                    : g_ebL + (size_t)(ncb + col) * 32 + (part - 8) * 4);
                cp16(bufW + dstW * 4, src);
            }
            CP_COMMIT();
        }

        // ---- acc init = -0.5*||e||^2 ----
        float acc[4][2][4];
        #pragma unroll
        for (int nf = 0; nf < 2; nf++) {
            const int cl = cb + wn * 16 + nf * 8 + 2 * q;
            const float e0 = -0.5f * __ldg(g_en + cl);
            const float e1 = -0.5f * __ldg(g_en + cl + 1);
            #pragma unroll
            for (int mf = 0; mf < 4; mf++) {
                acc[mf][nf][0] = e0; acc[mf][nf][1] = e1;
                acc[mf][nf][2] = e0; acc[mf][nf][3] = e1;
            }
        }

        // ---- 12 K=16 steps: p0 hi*hi, p1 lo*hi, p2 hi*lo ----
        #pragma unroll 3
        for (int t = 0; t < 12; t++) {
            const int p = t >> 2, s = t & 3;
            const uint32_t aw = ((p == 1 ? 32 : 0) + 8 * s) * 4;
            const uint32_t bw = ((p == 2 ? 32 : 0) + 8 * s) * 4;
            uint32_t bb[4];
            ldm4(bb, bufR + bOff + bw);
            #pragma unroll
            for (int mf = 0; mf < 4; mf++) {
                uint32_t a[4];
                ldm4(a, aAddr0 + (uint32_t)(mf * 16 * WA) * 4 + aw);
                mma_f16(acc[mf][0], a, &bb[0]);
                mma_f16(acc[mf][1], a, &bb[2]);
            }
        }

        // ---- running argmax (score already includes norm) ----
        #pragma unroll
        for (int mf = 0; mf < 4; mf++) {
            #pragma unroll
            for (int nf = 0; nf < 2; nf++) {
                const int j0 = cb + wn * 16 + nf * 8 + 2 * q;
                float s0 = acc[mf][nf][0], s1 = acc[mf][nf][1];
                float s2 = acc[mf][nf][2], s3 = acc[mf][nf][3];
                if (s0 > best[2 * mf])     { best[2 * mf] = s0;     bidx[2 * mf] = j0; }
                if (s1 > best[2 * mf])     { best[2 * mf] = s1;     bidx[2 * mf] = j0 + 1; }
                if (s2 > best[2 * mf + 1]) { best[2 * mf + 1] = s2; bidx[2 * mf + 1] = j0; }
                if (s3 > best[2 * mf + 1]) { best[2 * mf + 1] = s3; bidx[2 * mf + 1] = j0 + 1; }
            }
        }
    }
    __syncthreads();

    // ---- cross-thread per-row reduction: 16 candidates per row ----
    float* sVal = (float*)(smw + SM_B0);
    int*   sIdx = (int*)(smw + SM_B0 + 2048);
    {
        const int slot = wn * 4 + q;
        #pragma unroll
        for (int i = 0; i < 8; i++) {
            const int mf = i >> 1, half = i & 1;
            const int r = wm * 64 + mf * 16 + g + half * 8;
            sVal[r * 16 + slot] = best[i];
            sIdx[r * 16 + slot] = bidx[i];
        }
    }
    __syncthreads();

    float dsum = 0.0f;
    if (tid < 128) {
        const int r = tid;
        float bv = sVal[r * 16];
        int   bj = sIdx[r * 16];
        #pragma unroll
        for (int t2 = 1; t2 < 16; t2++) {
            float v = sVal[r * 16 + t2];
            int   j = sIdx[r * 16 + t2];
            if (v > bv || (v == bv && j < bj)) { bv = v; bj = j; }
        }
        out[OFF_IND + rowBase + r] = (float)bj;
        atomicAdd(&g_count[bj], 1.0f);

        const float* ecol = embed + bj;
        const uint32_t* ar = As + r * WA;
        float* qout = out + (size_t)(rowBase + r) * DIM;
        #pragma unroll 8
        for (int kk = 0; kk < 32; kk++) {
            float2 h = __half22float2(*(const __half2*)&ar[kk]);
            float2 l = __half22float2(*(const __half2*)&ar[32 + kk]);
            float xv0 = h.x + l.x, xv1 = h.y + l.y;
            float q0 = ecol[(2 * kk) * NE];
            float q1 = ecol[(2 * kk + 1) * NE];
            float d0 = q0 - xv0, d1 = q1 - xv1;
            dsum = fmaf(d0, d0, fmaf(d1, d1, dsum));
            qout[2 * kk]     = q0;
            qout[2 * kk + 1] = q1;
            atomicAdd(&g_esum[bj * 64 + 2 * kk],     xv0);
            atomicAdd(&g_esum[bj * 64 + 2 * kk + 1], xv1);
        }
        #pragma unroll
        for (int o = 16; o; o >>= 1) dsum += __shfl_xor_sync(0xffffffffu, dsum, o);
        if ((tid & 31) == 0) atomicAdd(&g_diff, (double)dsum);
    }
}

// ------------------------------------------------------------------
__global__ void k2a(const float* __restrict__ cluster_size, float* __restrict__ out)
{
    __shared__ double ssum[32];
    int j = threadIdx.x;   // 1024 threads

    float ncs = DECAYF * cluster_size[j] + ONE_M_D * g_count[j];
    out[OFF_NCS + j] = ncs;
    g_count[j] = 0.0f;

    double v = (double)ncs;
    #pragma unroll
    for (int o = 16; o; o >>= 1) v += __shfl_xor_sync(0xffffffffu, v, o);
    if ((j & 31) == 0) ssum[j >> 5] = v;
    __syncthreads();
    if (j < 32) {
        double t = ssum[j];
        #pragma unroll
        for (int o = 16; o; o >>= 1) t += __shfl_xor_sync(0xffffffffu, t, o);
        if (j == 0) {
            g_n = (float)t;
            out[OFF_DIFF] = (float)(g_diff * (1.0 / 8388608.0));
            g_diff = 0.0;
        }
    }
}

__global__ void k2b(const float* __restrict__ embed_avg, float* __restrict__ out)
{
    const int k = blockIdx.x;
    const int j = threadIdx.x;
    const float n = g_n;
    const float ncs = out[OFF_NCS + j];
    const float cs = (ncs + EPSF) / (n + (float)NE * EPSF) * n;
    const float ea = DECAYF * embed_avg[k * NE + j] + ONE_M_D * g_esum[j * 64 + k];
    out[OFF_NEA + k * NE + j] = ea;
    out[OFF_NE  + k * NE + j] = ea / cs;
    g_esum[j * 64 + k] = 0.0f;
}

__global__ void kdummy() {}

// ------------------------------------------------------------------
extern "C" void kernel_launch(void* const* d_in, const int* in_sizes, int n_in,
                              void* d_out, int out_size) {
    const float* x            = (const float*)d_in[0];
    const float* embed        = (const float*)d_in[1];
    const float* cluster_size = (const float*)d_in[2];
    const float* embed_avg    = (const float*)d_in[3];
    float* out = (float*)d_out;

    cudaFuncSetAttribute(k1_main, cudaFuncAttributeMaxDynamicSharedMemorySize, SMEM_BYTES);

    // keep k1 at launch index 3 so the ncu window lands on it
    kdummy<<<1, 32>>>();
    kdummy<<<1, 32>>>();
    k0pre<<<8, 128>>>(embed);
    k1_main<<<NROWS / 128, 256, SMEM_BYTES>>>(x, embed, out);
    k2a<<<1, 1024>>>(cluster_size, out);
    k2b<<<64, 1024>>>(embed_avg, out);
}

// round 10
// speedup vs baseline: 1.1026x; 1.1026x over previous
#include <cuda_runtime.h>
#include <cuda_fp16.h>
#include <cstdint>

#define NROWS   131072
#define DIM     64
#define NE      1024
#define DECAYF  0.99f
#define ONE_M_D 0.01f
#define EPSF    1e-5f

// output layout (float32), tuple order of reference
#define OFF_Q    0
#define OFF_DIFF 8388608
#define OFF_IND  8388609
#define OFF_NCS  8519681
#define OFF_NEA  8520705
#define OFF_NE   8586241

// device scratch (statically zero-initialized; k2a/k2b re-zero after use)
__device__ float    g_count[NE];
__device__ float    g_esum[NE * DIM];
__device__ double   g_diff;
__device__ float    g_n;
// precomputed fp16 split of embed (col-major: [col][k-pair word])
__device__ uint32_t g_ebH[NE * 32];
__device__ uint32_t g_ebL[NE * 32];
__device__ float    g_en[NE];

// ------------------------------------------------------------------
__device__ __forceinline__ void mma_f16(float* c, const uint32_t* a, const uint32_t* b) {
    asm volatile(
        "mma.sync.aligned.m16n8k16.row.col.f32.f16.f16.f32 "
        "{%0,%1,%2,%3}, {%4,%5,%6,%7}, {%8,%9}, {%0,%1,%2,%3};"
        : "+f"(c[0]), "+f"(c[1]), "+f"(c[2]), "+f"(c[3])
        : "r"(a[0]), "r"(a[1]), "r"(a[2]), "r"(a[3]),
          "r"(b[0]), "r"(b[1]));
}
__device__ __forceinline__ void ldm4(uint32_t* r, uint32_t addr) {
    asm volatile("ldmatrix.sync.aligned.m8n8.x4.shared.b16 {%0,%1,%2,%3}, [%4];"
        : "=r"(r[0]), "=r"(r[1]), "=r"(r[2]), "=r"(r[3]) : "r"(addr));
}
__device__ __forceinline__ uint32_t h2(float a, float b) {
    __half2 h = __floats2half2_rn(a, b);
    return *(uint32_t*)&h;
}
__device__ __forceinline__ uint32_t smem_u32(const void* p) {
    uint32_t a;
    asm("{ .reg .u64 t; cvta.to.shared.u64 t, %1; cvt.u32.u64 %0, t; }" : "=r"(a) : "l"(p));
    return a;
}
__device__ __forceinline__ void cp16(uint32_t s, const void* g) {
    asm volatile("cp.async.cg.shared.global [%0], [%1], 16;" :: "r"(s), "l"(g));
}
#define CP_COMMIT() asm volatile("cp.async.commit_group;" ::: "memory")
#define CP_WAIT0()  asm volatile("cp.async.wait_group 0;" ::: "memory")

// ------------------------------------------------------------------
// SMEM (32-bit words): A [128 rows][68], B double buffer [128 cols][68] each
//   words 0..31 = fp16-hi pairs, 32..63 = fp16-lo pairs, 64..67 pad
#define WA 68
#define SM_A   0
#define SM_B0  (128 * WA)                  // 8704
#define SM_B1  (SM_B0 + 128 * WA)          // 17408
#define SMEM_WORDS (SM_B1 + 128 * WA)      // 26112
#define SMEM_BYTES (SMEM_WORDS * 4)        // 104448

#define NC 128
#define NCH 8

// ------------------------------------------------------------------
// k0: fp16-split of embed + col norms (runs once per launch)
// ------------------------------------------------------------------
__global__ void k0pre(const float* __restrict__ embed) {
    const int j = blockIdx.x * 128 + threadIdx.x;   // 1024 threads
    float en = 0.0f;
    #pragma unroll 8
    for (int w = 0; w < 32; w++) {
        float v0 = embed[(2 * w) * NE + j];
        float v1 = embed[(2 * w + 1) * NE + j];
        en = fmaf(v0, v0, fmaf(v1, v1, en));
        uint32_t hw = h2(v0, v1);
        __half2 hh = *(__half2*)&hw;
        float2 f = __half22float2(hh);
        g_ebH[j * 32 + w] = hw;
        g_ebL[j * 32 + w] = h2(v0 - f.x, v1 - f.y);
    }
    g_en[j] = en;
}

// ------------------------------------------------------------------
// k1: fused fp16-split MMA distance + argmin + stats
//     frag-sharing inner loop: A-hi reused for (B-hi, B-lo), B-hi for A-lo
// ------------------------------------------------------------------
__global__ void __launch_bounds__(256, 2) k1_main(
    const float* __restrict__ x,
    const float* __restrict__ embed,
    float* __restrict__ out)
{
    extern __shared__ uint32_t smw[];
    uint32_t* As = smw + SM_A;
    const uint32_t smbA  = smem_u32(smw);
    const uint32_t smbB0 = smbA + SM_B0 * 4;
    const uint32_t smbB1 = smbA + SM_B1 * 4;

    const int tid  = threadIdx.x;
    const int wid  = tid >> 5;
    const int lane = tid & 31;
    const int g    = lane >> 2;
    const int q    = lane & 3;
    const int wm   = wid >> 2;      // 0..1
    const int wn   = wid & 3;       // 0..3
    const int rowBase = blockIdx.x * 128;

    // ---- prefetch B chunk 0 into buf0 ----
    #pragma unroll
    for (int it = 0; it < 8; ++it) {
        const int task = tid + it * 256;
        const int col = task >> 4, part = task & 15;
        const uint32_t dstW = col * WA + (part < 8 ? part * 4 : 32 + (part - 8) * 4);
        const uint32_t* src = (part < 8 ? g_ebH + (size_t)col * 32 + part * 4
                                        : g_ebL + (size_t)col * 32 + (part - 8) * 4);
        cp16(smbB0 + dstW * 4, src);
    }
    CP_COMMIT();

    // ---- load A: fp16 split of x tile ----
    {
        const int r = tid >> 1, half = tid & 1;
        const float4* xg = (const float4*)(x + (size_t)(rowBase + r) * DIM) + half * 8;
        uint32_t* dA = As + r * WA + half * 16;
        #pragma unroll
        for (int i = 0; i < 8; i++) {
            float4 v = xg[i];
            uint32_t hxy = h2(v.x, v.y), hzw = h2(v.z, v.w);
            __half2 hh0 = *(__half2*)&hxy, hh1 = *(__half2*)&hzw;
            float2 f0 = __half22float2(hh0), f1 = __half22float2(hh1);
            dA[2 * i]          = hxy;
            dA[2 * i + 1]      = hzw;
            dA[32 + 2 * i]     = h2(v.x - f0.x, v.y - f0.y);
            dA[32 + 2 * i + 1] = h2(v.z - f1.x, v.w - f1.y);
        }
    }

    // per-lane ldmatrix addresses
    const int r8  = lane & 7;
    const int sel = lane >> 3;      // 0..3
    uint32_t aAddr[4];
    #pragma unroll
    for (int mf = 0; mf < 4; mf++) {
        const int row = wm * 64 + mf * 16 + r8 + (sel & 1) * 8;
        aAddr[mf] = smbA + (uint32_t)(row * WA + (sel >> 1) * 4) * 4;
    }
    const uint32_t bOff0 = (uint32_t)((wn * 32 + r8 + (sel >> 1) * 8) * WA + (sel & 1) * 4) * 4;
    const uint32_t bOff1 = bOff0 + (uint32_t)(16 * WA) * 4;

    float best[8];
    int   bidx[8];
    #pragma unroll
    for (int i = 0; i < 8; i++) { best[i] = -3.4e38f; bidx[i] = 0; }

    for (int c = 0; c < NCH; c++) {
        const int cb = c * NC;
        const uint32_t bufR = (c & 1) ? smbB1 : smbB0;
        const uint32_t bufW = (c & 1) ? smbB0 : smbB1;

        CP_WAIT0();
        __syncthreads();

        // ---- prefetch chunk c+1 (other buffer), overlaps MMA ----
        if (c < NCH - 1) {
            const int ncb = cb + NC;
            #pragma unroll
            for (int it = 0; it < 8; ++it) {
                const int task = tid + it * 256;
                const int col = task >> 4, part = task & 15;
                const uint32_t dstW = col * WA + (part < 8 ? part * 4 : 32 + (part - 8) * 4);
                const uint32_t* src = (part < 8
                    ? g_ebH + (size_t)(ncb + col) * 32 + part * 4
                    : g_ebL + (size_t)(ncb + col) * 32 + (part - 8) * 4);
                cp16(bufW + dstW * 4, src);
            }
            CP_COMMIT();
        }

        // ---- acc init = -0.5*||e||^2 ----
        float acc[4][4][4];
        #pragma unroll
        for (int nf = 0; nf < 4; nf++) {
            const int cl = cb + wn * 32 + nf * 8 + 2 * q;
            const float e0 = -0.5f * __ldg(g_en + cl);
            const float e1 = -0.5f * __ldg(g_en + cl + 1);
            #pragma unroll
            for (int mf = 0; mf < 4; mf++) {
                acc[mf][nf][0] = e0; acc[mf][nf][1] = e1;
                acc[mf][nf][2] = e0; acc[mf][nf][3] = e1;
            }
        }

        // ---- 4 k-slices; shared frags: A-hi x {B-hi,B-lo}, A-lo x B-hi ----
        #pragma unroll
        for (int s = 0; s < 4; s++) {
            const uint32_t awH = (uint32_t)(8 * s) * 4;
            const uint32_t awL = awH + 32 * 4;

            uint32_t A[4][4];
            #pragma unroll
            for (int mf = 0; mf < 4; mf++) ldm4(A[mf], aAddr[mf] + awH);
            uint32_t BH[2][4], BL[2][4];
            ldm4(BH[0], bufR + bOff0 + awH);
            ldm4(BH[1], bufR + bOff1 + awH);
            ldm4(BL[0], bufR + bOff0 + awL);
            ldm4(BL[1], bufR + bOff1 + awL);

            // hi * hi
            #pragma unroll
            for (int mf = 0; mf < 4; mf++)
                #pragma unroll
                for (int nf = 0; nf < 4; nf++)
                    mma_f16(acc[mf][nf], A[mf], &BH[nf >> 1][(nf & 1) * 2]);
            // hi * lo
            #pragma unroll
            for (int mf = 0; mf < 4; mf++)
                #pragma unroll
                for (int nf = 0; nf < 4; nf++)
                    mma_f16(acc[mf][nf], A[mf], &BL[nf >> 1][(nf & 1) * 2]);
            // reload A as lo, then lo * hi
            #pragma unroll
            for (int mf = 0; mf < 4; mf++) ldm4(A[mf], aAddr[mf] + awL);
            #pragma unroll
            for (int mf = 0; mf < 4; mf++)
                #pragma unroll
                for (int nf = 0; nf < 4; nf++)
                    mma_f16(acc[mf][nf], A[mf], &BH[nf >> 1][(nf & 1) * 2]);
        }

        // ---- running argmax (score already includes norm) ----
        #pragma unroll
        for (int mf = 0; mf < 4; mf++) {
            #pragma unroll
            for (int nf = 0; nf < 4; nf++) {
                const int j0 = cb + wn * 32 + nf * 8 + 2 * q;
                float s0 = acc[mf][nf][0], s1 = acc[mf][nf][1];
                float s2 = acc[mf][nf][2], s3 = acc[mf][nf][3];
                if (s0 > best[2 * mf])     { best[2 * mf] = s0;     bidx[2 * mf] = j0; }
                if (s1 > best[2 * mf])     { best[2 * mf] = s1;     bidx[2 * mf] = j0 + 1; }
                if (s2 > best[2 * mf + 1]) { best[2 * mf + 1] = s2; bidx[2 * mf + 1] = j0; }
                if (s3 > best[2 * mf + 1]) { best[2 * mf + 1] = s3; bidx[2 * mf + 1] = j0 + 1; }
            }
        }
    }
    __syncthreads();

    // ---- cross-thread per-row reduction: 16 candidates per row ----
    float* sVal = (float*)(smw + SM_B0);
    int*   sIdx = (int*)(smw + SM_B0 + 2048);
    {
        const int slot = wn * 4 + q;
        #pragma unroll
        for (int i = 0; i < 8; i++) {
            const int mf = i >> 1, half = i & 1;
            const int r = wm * 64 + mf * 16 + g + half * 8;
            sVal[r * 16 + slot] = best[i];
            sIdx[r * 16 + slot] = bidx[i];
        }
    }
    __syncthreads();

    float dsum = 0.0f;
    if (tid < 128) {
        const int r = tid;
        float bv = sVal[r * 16];
        int   bj = sIdx[r * 16];
        #pragma unroll
        for (int t2 = 1; t2 < 16; t2++) {
            float v = sVal[r * 16 + t2];
            int   j = sIdx[r * 16 + t2];
            if (v > bv || (v == bv && j < bj)) { bv = v; bj = j; }
        }
        out[OFF_IND + rowBase + r] = (float)bj;
        atomicAdd(&g_count[bj], 1.0f);

        const float* ecol = embed + bj;
        const uint32_t* ar = As + r * WA;
        float* qout = out + (size_t)(rowBase + r) * DIM;
        #pragma unroll 8
        for (int kk = 0; kk < 32; kk++) {
            float2 h = __half22float2(*(const __half2*)&ar[kk]);
            float2 l = __half22float2(*(const __half2*)&ar[32 + kk]);
            float xv0 = h.x + l.x, xv1 = h.y + l.y;
            float q0 = ecol[(2 * kk) * NE];
            float q1 = ecol[(2 * kk + 1) * NE];
            float d0 = q0 - xv0, d1 = q1 - xv1;
            dsum = fmaf(d0, d0, fmaf(d1, d1, dsum));
            qout[2 * kk]     = q0;
            qout[2 * kk + 1] = q1;
            atomicAdd(&g_esum[bj * 64 + 2 * kk],     xv0);
            atomicAdd(&g_esum[bj * 64 + 2 * kk + 1], xv1);
        }
        #pragma unroll
        for (int o = 16; o; o >>= 1) dsum += __shfl_xor_sync(0xffffffffu, dsum, o);
        if ((tid & 31) == 0) atomicAdd(&g_diff, (double)dsum);
    }
}

// ------------------------------------------------------------------
__global__ void k2a(const float* __restrict__ cluster_size, float* __restrict__ out)
{
    __shared__ double ssum[32];
    int j = threadIdx.x;   // 1024 threads

    float ncs = DECAYF * cluster_size[j] + ONE_M_D * g_count[j];
    out[OFF_NCS + j] = ncs;
    g_count[j] = 0.0f;

    double v = (double)ncs;
    #pragma unroll
    for (int o = 16; o; o >>= 1) v += __shfl_xor_sync(0xffffffffu, v, o);
    if ((j & 31) == 0) ssum[j >> 5] = v;
    __syncthreads();
    if (j < 32) {
        double t = ssum[j];
        #pragma unroll
        for (int o = 16; o; o >>= 1) t += __shfl_xor_sync(0xffffffffu, t, o);
        if (j == 0) {
            g_n = (float)t;
            out[OFF_DIFF] = (float)(g_diff * (1.0 / 8388608.0));
            g_diff = 0.0;
        }
    }
}

__global__ void k2b(const float* __restrict__ embed_avg, float* __restrict__ out)
{
    const int k = blockIdx.x;
    const int j = threadIdx.x;
    const float n = g_n;
    const float ncs = out[OFF_NCS + j];
    const float cs = (ncs + EPSF) / (n + (float)NE * EPSF) * n;
    const float ea = DECAYF * embed_avg[k * NE + j] + ONE_M_D * g_esum[j * 64 + k];
    out[OFF_NEA + k * NE + j] = ea;
    out[OFF_NE  + k * NE + j] = ea / cs;
    g_esum[j * 64 + k] = 0.0f;
}

__global__ void kdummy() {}

// ------------------------------------------------------------------
extern "C" void kernel_launch(void* const* d_in, const int* in_sizes, int n_in,
                              void* d_out, int out_size) {
    const float* x            = (const float*)d_in[0];
    const float* embed        = (const float*)d_in[1];
    const float* cluster_size = (const float*)d_in[2];
    const float* embed_avg    = (const float*)d_in[3];
    float* out = (float*)d_out;

    cudaFuncSetAttribute(k1_main, cudaFuncAttributeMaxDynamicSharedMemorySize, SMEM_BYTES);

    // keep k1 at launch index 3 so the ncu window lands on it
    kdummy<<<1, 32>>>();
    kdummy<<<1, 32>>>();
    k0pre<<<8, 128>>>(embed);
    k1_main<<<NROWS / 128, 256, SMEM_BYTES>>>(x, embed, out);
    k2a<<<1, 1024>>>(cluster_size, out);
    k2b<<<64, 1024>>>(embed_avg, out);
}